// round 13
// baseline (speedup 1.0000x reference)
#include <cuda_runtime.h>
#include <cuda_fp16.h>
#include <cstdint>

// Problem constants
#define B_   256
#define CIN  64
#define COUT 128
#define H_   1039
#define KN   6          // max neighbors
#define KT   7          // center + neighbors

// Static device scratch (allocation-guard safe)
__device__ __align__(256) __half g_x[(size_t)H_ * B_ * CIN];    // [h][b][c] fp16
__device__ __align__(256) __half g_wfrag[KT * COUT * CIN];      // fragment-order fp16
__device__ __align__(256) __half g_tmp[(size_t)H_ * COUT * B_]; // [h][o][b] fp16 (post scale+bias)

// ---------------------------------------------------------------------------
// PTX helpers (baseline ISA only — toolchain lowers through compute_103)
// ---------------------------------------------------------------------------
__device__ __forceinline__ uint32_t smem_u32(const void* p) {
    uint32_t r;
    asm("{ .reg .u64 t; cvta.to.shared.u64 t, %1; cvt.u32.u64 %0, t; }"
        : "=r"(r) : "l"(p));
    return r;
}
__device__ __forceinline__ void cpasync16(uint32_t s, const void* g) {
    asm volatile("cp.async.ca.shared.global [%0], [%1], 16;"
                 :: "r"(s), "l"(g) : "memory");
}
#define CP_COMMIT() asm volatile("cp.async.commit_group;" ::: "memory")
#define CP_WAIT(n)  asm volatile("cp.async.wait_group %0;" :: "n"(n) : "memory")

#define LDSM_X4(r, addr) \
    asm volatile("ldmatrix.sync.aligned.m8n8.x4.shared.b16 {%0,%1,%2,%3}, [%4];" \
                 : "=r"((r)[0]), "=r"((r)[1]), "=r"((r)[2]), "=r"((r)[3]) \
                 : "r"(addr))

__device__ __forceinline__ void mma_fp16(float* c, const uint32_t* a,
                                         uint32_t b0, uint32_t b1) {
    asm volatile(
        "mma.sync.aligned.m16n8k16.row.col.f32.f16.f16.f32 "
        "{%0,%1,%2,%3}, {%4,%5,%6,%7}, {%8,%9}, {%0,%1,%2,%3};"
        : "+f"(c[0]), "+f"(c[1]), "+f"(c[2]), "+f"(c[3])
        : "r"(a[0]), "r"(a[1]), "r"(a[2]), "r"(a[3]), "r"(b0), "r"(b1));
}

// ---------------------------------------------------------------------------
// Kernel 1: x[b][c][h] (viewed [m=bc][h]) -> g_x[h][m] fp16
// ---------------------------------------------------------------------------
__global__ void k_prep_x(const float* __restrict__ x) {
    __shared__ float t[32][33];
    const int h0 = blockIdx.x * 32;
    const int m0 = blockIdx.y * 32;
    const int tx = threadIdx.x, ty = threadIdx.y;

#pragma unroll
    for (int i = 0; i < 32; i += 8) {
        int h = h0 + tx;
        if (h < H_)
            t[ty + i][tx] = x[(size_t)(m0 + ty + i) * H_ + h];
    }
    __syncthreads();
#pragma unroll
    for (int i = 0; i < 32; i += 8) {
        int h = h0 + ty + i;
        int m = m0 + tx;
        if (h < H_)
            g_x[(size_t)h * (B_ * CIN) + m] = __float2half(t[tx][ty + i]);
    }
}

// ---------------------------------------------------------------------------
// Kernel 2: pack weights into per-lane MMA fragment order (fp16).
// ---------------------------------------------------------------------------
__global__ void k_pack_w(const float* __restrict__ wc, const float* __restrict__ wn) {
    int t = blockIdx.x * blockDim.x + threadIdx.x;
    if (t >= KT * COUT * CIN) return;
    int k    = t >> 13;
    int rem  = t & 8191;
    int mi   = rem >> 10;
    int rem2 = rem & 1023;
    int ks   = rem2 >> 8;
    int rem3 = rem2 & 255;
    int ln   = rem3 >> 3;
    int e    = rem3 & 7;
    int j    = e >> 1;
    int hh   = e & 1;
    int o = mi * 16 + (j & 1) * 8 + (ln >> 2);
    int c = ks * 16 + ((j >> 1) & 1) * 8 + (ln & 3) * 2 + hh;
    float v = (k == 0) ? wc[o * CIN + c]
                       : wn[(o * CIN + c) * KN + (k - 1)];
    g_wfrag[t] = __float2half(v);
}

// ---------------------------------------------------------------------------
// Kernel 3: main HMMA GEMM (R9 winner — ~92% of legacy-HMMA ceiling).
// Grid (2 b-halves, H). CTA tile o=128 x b=128. 8 warps, warp tile 32(o) x
// 64(b). Single fp16 term, fp32 accumulate. 16KB B stages, 4-stage cp.async
// ring with distance-3 prefetch, one barrier per chunk, occupancy 2.
// ---------------------------------------------------------------------------
#define BT_BYTES 16384                    // 128 rows x 128B
#define NSTAGE 4
#define DSMEM_BYTES (NSTAGE * BT_BYTES + 1024)

extern __shared__ char dsm[];

// swizzled smem offset for (row, 16B-chunk c) within a tile of 128B rows
__device__ __forceinline__ uint32_t swz(uint32_t row, uint32_t c) {
    return row * 128u + ((c ^ (row & 7u)) * 16u);
}

__global__ void __launch_bounds__(256, 2)
k_main(const int* __restrict__ neighbors, const float* __restrict__ bias) {
    __shared__ int s_idx[KT];
    __shared__ int s_n;
    __shared__ float s_scale;

    const int h    = blockIdx.y;
    const int bh   = blockIdx.x;          // b-half: rows bh*128 .. bh*128+127
    const int tid  = threadIdx.x;
    const int wid  = tid >> 5;
    const int lane = tid & 31;
    const int wo   = wid & 3;             // o 32-row group
    const int wb   = wid >> 2;            // b 64-half within the 128

    const uint32_t sraw  = smem_u32(dsm);
    const uint32_t sbase = (sraw + 1023u) & ~1023u;

    if (tid == 0) {
        s_idx[0] = h;
        int n = 1;
#pragma unroll
        for (int k = 0; k < KN; ++k) {
            int v = neighbors[h * KN + k];
            if (v >= 0) s_idx[n++] = v;   // valid-prefix: slot i -> weight chunk i
        }
        s_n = n;
        s_scale = 1.0f / (float)n;
    }
    __syncthreads();

    const int n = s_n;                    // n in [4,7]
    const size_t boff = (size_t)bh * 128 * CIN;

    // ---- stage loader: chunk ci -> ring buffer j ----
    auto load_stage = [&](int ci, int j) {
        const char* Bsrc = (const char*)(g_x + (size_t)s_idx[ci] * (B_ * CIN) + boff);
        const uint32_t sb = sbase + (uint32_t)j * BT_BYTES;
#pragma unroll
        for (int p = 0; p < 4; ++p) {             // 1024 16B chunks
            int id = tid + p * 256;
            uint32_t sw = swz((uint32_t)(id >> 3), (uint32_t)(id & 7));
            cpasync16(sb + sw, Bsrc + (size_t)id * 16);
        }
    };

    float acc[2][8][4];
#pragma unroll
    for (int mi = 0; mi < 2; ++mi)
#pragma unroll
        for (int ni = 0; ni < 8; ++ni)
#pragma unroll
            for (int q = 0; q < 4; ++q) acc[mi][ni][q] = 0.0f;

    // prologue: 3 stages in flight (n >= 4 always)
    load_stage(0, 0); CP_COMMIT();
    load_stage(1, 1); CP_COMMIT();
    load_stage(2, 2); CP_COMMIT();

    const uint32_t b_lr = (uint32_t)((lane & 7) + ((lane & 16) >> 1)); // 0..15
    const uint32_t b_lc = (uint32_t)((lane >> 3) & 1);

    const uint4* __restrict__ wf = (const uint4*)g_wfrag;

    for (int i = 0; i < n; ++i) {
        if (i <= n - 3)      { CP_WAIT(2); }
        else if (i == n - 2) { CP_WAIT(1); }
        else                 { CP_WAIT(0); }
        __syncthreads();

        if (i + 3 < n) { load_stage(i + 3, (i + 3) % NSTAGE); CP_COMMIT(); }

        const uint32_t st = sbase + (uint32_t)(i % NSTAGE) * BT_BYTES;
        const uint4* wfk = wf + (size_t)i * 1024;

#pragma unroll
        for (int ks = 0; ks < 4; ++ks) {
            uint32_t a[2][4];
#pragma unroll
            for (int mi = 0; mi < 2; ++mi) {
                int MI = wo * 2 + mi;                         // o-row group 0..7
                uint4 v = wfk[((MI * 4 + ks) * 32) + lane];
                a[mi][0] = v.x; a[mi][1] = v.y; a[mi][2] = v.z; a[mi][3] = v.w;
            }
            uint32_t b[4][4];
#pragma unroll
            for (int nt = 0; nt < 4; ++nt) {
                uint32_t row = (uint32_t)(wb * 64 + nt * 16) + b_lr;
                LDSM_X4(b[nt], st + swz(row, (uint32_t)(ks * 2) + b_lc));
            }
#pragma unroll
            for (int mi = 0; mi < 2; ++mi)
#pragma unroll
                for (int nt = 0; nt < 4; ++nt) {
                    mma_fp16(acc[mi][2 * nt],     a[mi], b[nt][0], b[nt][1]);
                    mma_fp16(acc[mi][2 * nt + 1], a[mi], b[nt][2], b[nt][3]);
                }
        }
    }

    // ---- epilogue: scale + bias, fp16 store to g_tmp[h][o][b] ----
    const float sc = s_scale;
    const int r     = lane >> 2;
    const int cpair = (lane & 3) * 2;
#pragma unroll
    for (int mi = 0; mi < 2; ++mi) {
        const int o0 = wo * 32 + mi * 16 + r;
        const float bi0 = bias[o0];
        const float bi8 = bias[o0 + 8];
        __half* d0 = g_tmp + ((size_t)h * COUT + o0) * B_ + bh * 128 + wb * 64 + cpair;
        __half* d8 = d0 + 8 * B_;
#pragma unroll
        for (int ni = 0; ni < 8; ++ni) {
            __half2 v0 = __floats2half2_rn(acc[mi][ni][0] * sc + bi0,
                                           acc[mi][ni][1] * sc + bi0);
            __half2 v8 = __floats2half2_rn(acc[mi][ni][2] * sc + bi8,
                                           acc[mi][ni][3] * sc + bi8);
            *(__half2*)(d0 + ni * 8) = v0;
            *(__half2*)(d8 + ni * 8) = v8;
        }
    }
}

// ---------------------------------------------------------------------------
// Kernel 4: tmp[h][o][b] (fp16) -> out[b][o][h] (fp32)
// Tile 64(h) x 256(b = full B) per (h-tile, o) block; 2176 blocks total.
// Read: half2 128B-coalesced. Write: each thread owns a 16-h contiguous run
// of one output row -> alignment-phased float4 stores (H_ odd => per-row
// phase a = (-base)&3). Tail h-tile uses a bounded scalar path.
// ---------------------------------------------------------------------------
#define TP_S 133   // smem row stride in half2 (16*133 % 32 == 16 -> <=2-way)

__global__ void __launch_bounds__(256)
k_transpose_out(float* __restrict__ out) {
    __shared__ __half2 t2[64][TP_S];      // [h_local][b_pair 0..127]
    const int o   = blockIdx.y;
    const int h0  = blockIdx.x * 64;
    const int tid = threadIdx.x;

    // ---- read: 32 passes; cp fixed, rows advance by 2 ----
    {
        const int cp   = tid & 127;        // half2 index within 256 b
        const int row0 = tid >> 7;         // 0..1
        const __half* src = g_tmp + ((size_t)(h0 + row0) * COUT + o) * B_ + 2 * cp;
        const size_t sstep = (size_t)2 * COUT * B_;
#pragma unroll
        for (int p = 0; p < 32; ++p) {
            int row = row0 + 2 * p;
            if (h0 + row < H_)
                t2[row][cp] = *(const __half2*)(src + p * sstep);
        }
    }
    __syncthreads();

    // ---- write: 4 groups; thread = (b-row, 16-h chunk t) ----
    {
        const int blq = tid >> 2;          // 0..63: b-row within group
        const int t   = tid & 3;           // 16-h chunk
        const int hs  = t * 16;            // h offset within tile
        const int h_start = h0 + hs;
        const int hi = (blq & 1);          // b parity (pass-invariant)

#pragma unroll
        for (int g = 0; g < 4; ++g) {
            const int b = g * 64 + blq;
            const int bp = b >> 1;
            if (h_start < H_) {
                const size_t base = ((size_t)b * COUT + o) * (size_t)H_;
                float* dst = out + base + h_start;
                // gather 16 values from smem
                float v[16];
#pragma unroll
                for (int j = 0; j < 16; ++j) {
                    __half2 w = t2[hs + j][bp];
                    v[j] = hi ? __high2float(w) : __low2float(w);
                }
                if (h_start + 16 <= H_) {
                    const int a = (int)((0u - (uint32_t)((base + (size_t)h_start) & 3u)) & 3u);
#pragma unroll
                    for (int j = 0; j < 3; ++j)
                        if (j < a) dst[j] = v[j];
                    const int nv = (16 - a) >> 2;
#pragma unroll
                    for (int q = 0; q < 4; ++q) {
                        if (q < nv) {
                            float4 f4 = make_float4(v[a + 4 * q], v[a + 4 * q + 1],
                                                    v[a + 4 * q + 2], v[a + 4 * q + 3]);
                            *(float4*)(dst + a + 4 * q) = f4;
                        }
                    }
                    const int tr = (4 - a) & 3;
#pragma unroll
                    for (int j = 0; j < 3; ++j)
                        if (j < tr) dst[a + 4 * nv + j] = v[a + 4 * nv + j];
                } else {
                    const int nvalid = H_ - h_start;   // 1..15
#pragma unroll
                    for (int j = 0; j < 16; ++j)
                        if (j < nvalid) dst[j] = v[j];
                }
            }
        }
    }
}

// ---------------------------------------------------------------------------
// Launch
// Inputs: x[f32], neighbors[int32], weight_center[f32], weight_neighbors[f32],
//         bias[f32]
// ---------------------------------------------------------------------------
extern "C" void kernel_launch(void* const* d_in, const int* in_sizes, int n_in,
                              void* d_out, int out_size) {
    const float* x    = (const float*)d_in[0];
    const int*   nb   = (const int*)d_in[1];
    const float* wc   = (const float*)d_in[2];
    const float* wn   = (const float*)d_in[3];
    const float* bias = (const float*)d_in[4];
    float* out = (float*)d_out;

    // 1) transpose + fp16 convert of x
    k_prep_x<<<dim3((H_ + 31) / 32, (B_ * CIN) / 32), dim3(32, 8)>>>(x);

    // 2) pack weights into fragment order
    k_pack_w<<<(KT * COUT * CIN + 255) / 256, 256>>>(wc, wn);

    // 3) main HMMA GEMM, 2 CTAs per hexagon (b-halves)
    cudaFuncSetAttribute(k_main, cudaFuncAttributeMaxDynamicSharedMemorySize,
                         DSMEM_BYTES);
    k_main<<<dim3(2, H_), 256, DSMEM_BYTES>>>(nb, bias);

    // 4) transpose tmp -> out (64h x 256b tiles, one per (h-tile, o))
    k_transpose_out<<<dim3((H_ + 63) / 64, COUT), 256>>>(out);
}

// round 15
// speedup vs baseline: 1.2920x; 1.2920x over previous
#include <cuda_runtime.h>
#include <cuda_fp16.h>
#include <cstdint>

// Problem constants
#define B_   256
#define CIN  64
#define COUT 128
#define H_   1039
#define KN   6          // max neighbors
#define KT   7          // center + neighbors

// Static device scratch (allocation-guard safe)
__device__ __align__(256) __half g_x[(size_t)H_ * B_ * CIN];    // [h][b][c] fp16
__device__ __align__(256) __half g_wfrag[KT * COUT * CIN];      // fragment-order fp16
__device__ __align__(256) __half g_tmp[(size_t)H_ * COUT * B_]; // [h][o][b] fp16 (post scale+bias)

// ---------------------------------------------------------------------------
// PTX helpers (baseline ISA only — toolchain lowers through compute_103)
// ---------------------------------------------------------------------------
__device__ __forceinline__ uint32_t smem_u32(const void* p) {
    uint32_t r;
    asm("{ .reg .u64 t; cvta.to.shared.u64 t, %1; cvt.u32.u64 %0, t; }"
        : "=r"(r) : "l"(p));
    return r;
}
__device__ __forceinline__ void cpasync16(uint32_t s, const void* g) {
    asm volatile("cp.async.ca.shared.global [%0], [%1], 16;"
                 :: "r"(s), "l"(g) : "memory");
}
#define CP_COMMIT() asm volatile("cp.async.commit_group;" ::: "memory")
#define CP_WAIT(n)  asm volatile("cp.async.wait_group %0;" :: "n"(n) : "memory")

#define LDSM_X4(r, addr) \
    asm volatile("ldmatrix.sync.aligned.m8n8.x4.shared.b16 {%0,%1,%2,%3}, [%4];" \
                 : "=r"((r)[0]), "=r"((r)[1]), "=r"((r)[2]), "=r"((r)[3]) \
                 : "r"(addr))

__device__ __forceinline__ void mma_fp16(float* c, const uint32_t* a,
                                         uint32_t b0, uint32_t b1) {
    asm volatile(
        "mma.sync.aligned.m16n8k16.row.col.f32.f16.f16.f32 "
        "{%0,%1,%2,%3}, {%4,%5,%6,%7}, {%8,%9}, {%0,%1,%2,%3};"
        : "+f"(c[0]), "+f"(c[1]), "+f"(c[2]), "+f"(c[3])
        : "r"(a[0]), "r"(a[1]), "r"(a[2]), "r"(a[3]), "r"(b0), "r"(b1));
}

// ---------------------------------------------------------------------------
// Kernel 1: x[b][c][h] (viewed [m=bc][h]) -> g_x[h][m] fp16
// ---------------------------------------------------------------------------
__global__ void k_prep_x(const float* __restrict__ x) {
    __shared__ float t[32][33];
    const int h0 = blockIdx.x * 32;
    const int m0 = blockIdx.y * 32;
    const int tx = threadIdx.x, ty = threadIdx.y;

#pragma unroll
    for (int i = 0; i < 32; i += 8) {
        int h = h0 + tx;
        if (h < H_)
            t[ty + i][tx] = x[(size_t)(m0 + ty + i) * H_ + h];
    }
    __syncthreads();
#pragma unroll
    for (int i = 0; i < 32; i += 8) {
        int h = h0 + ty + i;
        int m = m0 + tx;
        if (h < H_)
            g_x[(size_t)h * (B_ * CIN) + m] = __float2half(t[tx][ty + i]);
    }
}

// ---------------------------------------------------------------------------
// Kernel 2: pack weights into per-lane MMA fragment order (fp16).
// ---------------------------------------------------------------------------
__global__ void k_pack_w(const float* __restrict__ wc, const float* __restrict__ wn) {
    int t = blockIdx.x * blockDim.x + threadIdx.x;
    if (t >= KT * COUT * CIN) return;
    int k    = t >> 13;
    int rem  = t & 8191;
    int mi   = rem >> 10;
    int rem2 = rem & 1023;
    int ks   = rem2 >> 8;
    int rem3 = rem2 & 255;
    int ln   = rem3 >> 3;
    int e    = rem3 & 7;
    int j    = e >> 1;
    int hh   = e & 1;
    int o = mi * 16 + (j & 1) * 8 + (ln >> 2);
    int c = ks * 16 + ((j >> 1) & 1) * 8 + (ln & 3) * 2 + hh;
    float v = (k == 0) ? wc[o * CIN + c]
                       : wn[(o * CIN + c) * KN + (k - 1)];
    g_wfrag[t] = __float2half(v);
}

// ---------------------------------------------------------------------------
// Kernel 3: main HMMA GEMM (R9/R11 winner — ~93% of legacy-HMMA ceiling).
// Grid (2 b-halves, H). CTA tile o=128 x b=128. 8 warps, warp tile 32(o) x
// 64(b). Single fp16 term, fp32 accumulate. 16KB B stages, 4-stage cp.async
// ring with distance-3 prefetch, one barrier per chunk, occupancy 2.
// ---------------------------------------------------------------------------
#define BT_BYTES 16384                    // 128 rows x 128B
#define NSTAGE 4
#define DSMEM_BYTES (NSTAGE * BT_BYTES + 1024)

extern __shared__ char dsm[];

// swizzled smem offset for (row, 16B-chunk c) within a tile of 128B rows
__device__ __forceinline__ uint32_t swz(uint32_t row, uint32_t c) {
    return row * 128u + ((c ^ (row & 7u)) * 16u);
}

__global__ void __launch_bounds__(256, 2)
k_main(const int* __restrict__ neighbors, const float* __restrict__ bias) {
    __shared__ int s_idx[KT];
    __shared__ int s_n;
    __shared__ float s_scale;

    const int h    = blockIdx.y;
    const int bh   = blockIdx.x;          // b-half: rows bh*128 .. bh*128+127
    const int tid  = threadIdx.x;
    const int wid  = tid >> 5;
    const int lane = tid & 31;
    const int wo   = wid & 3;             // o 32-row group
    const int wb   = wid >> 2;            // b 64-half within the 128

    const uint32_t sraw  = smem_u32(dsm);
    const uint32_t sbase = (sraw + 1023u) & ~1023u;

    if (tid == 0) {
        s_idx[0] = h;
        int n = 1;
#pragma unroll
        for (int k = 0; k < KN; ++k) {
            int v = neighbors[h * KN + k];
            if (v >= 0) s_idx[n++] = v;   // valid-prefix: slot i -> weight chunk i
        }
        s_n = n;
        s_scale = 1.0f / (float)n;
    }
    __syncthreads();

    const int n = s_n;                    // n in [4,7]
    const size_t boff = (size_t)bh * 128 * CIN;

    // ---- stage loader: chunk ci -> ring buffer j ----
    auto load_stage = [&](int ci, int j) {
        const char* Bsrc = (const char*)(g_x + (size_t)s_idx[ci] * (B_ * CIN) + boff);
        const uint32_t sb = sbase + (uint32_t)j * BT_BYTES;
#pragma unroll
        for (int p = 0; p < 4; ++p) {             // 1024 16B chunks
            int id = tid + p * 256;
            uint32_t sw = swz((uint32_t)(id >> 3), (uint32_t)(id & 7));
            cpasync16(sb + sw, Bsrc + (size_t)id * 16);
        }
    };

    float acc[2][8][4];
#pragma unroll
    for (int mi = 0; mi < 2; ++mi)
#pragma unroll
        for (int ni = 0; ni < 8; ++ni)
#pragma unroll
            for (int q = 0; q < 4; ++q) acc[mi][ni][q] = 0.0f;

    // prologue: 3 stages in flight (n >= 4 always)
    load_stage(0, 0); CP_COMMIT();
    load_stage(1, 1); CP_COMMIT();
    load_stage(2, 2); CP_COMMIT();

    const uint32_t b_lr = (uint32_t)((lane & 7) + ((lane & 16) >> 1)); // 0..15
    const uint32_t b_lc = (uint32_t)((lane >> 3) & 1);

    const uint4* __restrict__ wf = (const uint4*)g_wfrag;

    for (int i = 0; i < n; ++i) {
        if (i <= n - 3)      { CP_WAIT(2); }
        else if (i == n - 2) { CP_WAIT(1); }
        else                 { CP_WAIT(0); }
        __syncthreads();

        if (i + 3 < n) { load_stage(i + 3, (i + 3) % NSTAGE); CP_COMMIT(); }

        const uint32_t st = sbase + (uint32_t)(i % NSTAGE) * BT_BYTES;
        const uint4* wfk = wf + (size_t)i * 1024;

#pragma unroll
        for (int ks = 0; ks < 4; ++ks) {
            uint32_t a[2][4];
#pragma unroll
            for (int mi = 0; mi < 2; ++mi) {
                int MI = wo * 2 + mi;                         // o-row group 0..7
                uint4 v = wfk[((MI * 4 + ks) * 32) + lane];
                a[mi][0] = v.x; a[mi][1] = v.y; a[mi][2] = v.z; a[mi][3] = v.w;
            }
            uint32_t b[4][4];
#pragma unroll
            for (int nt = 0; nt < 4; ++nt) {
                uint32_t row = (uint32_t)(wb * 64 + nt * 16) + b_lr;
                LDSM_X4(b[nt], st + swz(row, (uint32_t)(ks * 2) + b_lc));
            }
#pragma unroll
            for (int mi = 0; mi < 2; ++mi)
#pragma unroll
                for (int nt = 0; nt < 4; ++nt) {
                    mma_fp16(acc[mi][2 * nt],     a[mi], b[nt][0], b[nt][1]);
                    mma_fp16(acc[mi][2 * nt + 1], a[mi], b[nt][2], b[nt][3]);
                }
        }
    }

    // ---- epilogue: scale + bias, fp16 store to g_tmp[h][o][b] ----
    const float sc = s_scale;
    const int r     = lane >> 2;
    const int cpair = (lane & 3) * 2;
#pragma unroll
    for (int mi = 0; mi < 2; ++mi) {
        const int o0 = wo * 32 + mi * 16 + r;
        const float bi0 = bias[o0];
        const float bi8 = bias[o0 + 8];
        __half* d0 = g_tmp + ((size_t)h * COUT + o0) * B_ + bh * 128 + wb * 64 + cpair;
        __half* d8 = d0 + 8 * B_;
#pragma unroll
        for (int ni = 0; ni < 8; ++ni) {
            __half2 v0 = __floats2half2_rn(acc[mi][ni][0] * sc + bi0,
                                           acc[mi][ni][1] * sc + bi0);
            __half2 v8 = __floats2half2_rn(acc[mi][ni][2] * sc + bi8,
                                           acc[mi][ni][3] * sc + bi8);
            *(__half2*)(d0 + ni * 8) = v0;
            *(__half2*)(d8 + ni * 8) = v8;
        }
    }
}

// ---------------------------------------------------------------------------
// Kernel 4: tmp[h][o][b] (fp16) -> out[b][o][h] (fp32)  tiled transpose per o
// Tile 64(h) x 128(b), 256 threads, 32 elems/thread. Exactly R11's proven
// read scheme (half2, 128B/warp) and write scheme (lane->h, scalar coalesced
// stores, pass-invariant parity) — only the b-tile width doubled to halve
// per-block fixed overhead.
// ---------------------------------------------------------------------------
__global__ void __launch_bounds__(256)
k_transpose_out(float* __restrict__ out) {
    __shared__ __half2 t2[64][65];        // [h_local][b_pair 0..63]
    const int o  = blockIdx.z;
    const int h0 = blockIdx.x * 64;
    const int b0 = blockIdx.y * 128;
    const int tid = threadIdx.x;

    // ---- read: 16 passes; fixed (row0, cp) per thread, constant stride ----
    {
        const int cp   = tid & 63;         // half2 index within 128 b
        const int row0 = tid >> 6;         // 0..3
        const __half* src = g_tmp + ((size_t)(h0 + row0) * COUT + o) * B_ + b0 + 2 * cp;
        const size_t sstep = (size_t)4 * COUT * B_;   // 4 h rows
#pragma unroll
        for (int p = 0; p < 16; ++p) {
            if (h0 + row0 + p * 4 < H_)
                t2[row0 + p * 4][cp] = *(const __half2*)(src + p * sstep);
        }
    }
    __syncthreads();

    // ---- write: 32 passes; hl pass-invariant, bl = bl0 + 4q ----
    {
        const int hl  = tid & 63;          // 0..63 (pass-invariant: 256 = 4*64)
        const int bl0 = tid >> 6;          // 0..3
        const int h   = h0 + hl;
        if (h < H_) {
            float* dst = out + ((size_t)(b0 + bl0) * COUT + o) * H_ + h;
            const size_t dstep = (size_t)4 * COUT * H_;   // 4 b rows
            const bool hi = (bl0 & 1);     // parity of bl is pass-invariant
#pragma unroll
            for (int q = 0; q < 32; ++q) {
                __half2 v = t2[hl][(bl0 + 4 * q) >> 1];
                dst[q * dstep] = hi ? __high2float(v) : __low2float(v);
            }
        }
    }
}

// ---------------------------------------------------------------------------
// Launch
// Inputs: x[f32], neighbors[int32], weight_center[f32], weight_neighbors[f32],
//         bias[f32]
// ---------------------------------------------------------------------------
extern "C" void kernel_launch(void* const* d_in, const int* in_sizes, int n_in,
                              void* d_out, int out_size) {
    const float* x    = (const float*)d_in[0];
    const int*   nb   = (const int*)d_in[1];
    const float* wc   = (const float*)d_in[2];
    const float* wn   = (const float*)d_in[3];
    const float* bias = (const float*)d_in[4];
    float* out = (float*)d_out;

    // 1) transpose + fp16 convert of x
    k_prep_x<<<dim3((H_ + 31) / 32, (B_ * CIN) / 32), dim3(32, 8)>>>(x);

    // 2) pack weights into fragment order
    k_pack_w<<<(KT * COUT * CIN + 255) / 256, 256>>>(wc, wn);

    // 3) main HMMA GEMM, 2 CTAs per hexagon (b-halves)
    cudaFuncSetAttribute(k_main, cudaFuncAttributeMaxDynamicSharedMemorySize,
                         DSMEM_BYTES);
    k_main<<<dim3(2, H_), 256, DSMEM_BYTES>>>(nb, bias);

    // 4) transpose tmp -> out (64h x 128b tiles)
    k_transpose_out<<<dim3((H_ + 63) / 64, B_ / 128, COUT), 256>>>(out);
}